// round 1
// baseline (speedup 1.0000x reference)
#include <cuda_runtime.h>
#include <cstdint>

// Problem constants
#define Bc 4
#define Lc 8192
#define Dc 512
#define Hc 8
#define DKc 64
#define Ec 65          // DK + PD
#define Fc 520         // H * E
#define FP 528         // padded F (multiple of 16)
#define NSPLIT 16
#define LCHUNK (Lc / NSPLIT)   // 512

#define ATT_ELEMS ((size_t)Bc * Lc * Dc)          // 16,777,216
#define ATTN_ELEMS ((size_t)Bc * Hc * Ec * Ec)    // 135,200

// ---------------- scratch (device globals; no allocs allowed) ----------------
__device__ float g_P[3][(size_t)Bc * Lc * Dc];          // q/k/v projections
__device__ float g_QC[(size_t)Bc * Lc * FP];            // concat q (padded)
__device__ float g_KC[(size_t)Bc * Lc * FP];            // concat k (LN'd)
__device__ float g_VC[(size_t)Bc * Lc * FP];            // concat v (LN'd)
__device__ float g_part[(size_t)Bc * Hc * NSPLIT * Ec * Ec];
__device__ float g_W2[(size_t)Bc * FP * Dc];            // attn folded into fcW

// ============================================================================
// Kernel 1: projections  P[op] = X_op @ W_op^T + b_op   ("NT" SGEMM)
// 64x64x16 tile, 256 threads, 4x4 register micro-tile.
// grid: (Dc/64, M/64, 3)
// ============================================================================
__global__ void proj_gemm(const float* __restrict__ Xq, const float* __restrict__ Xk,
                          const float* __restrict__ Xv,
                          const float* __restrict__ Wq, const float* __restrict__ bq,
                          const float* __restrict__ Wk, const float* __restrict__ bk,
                          const float* __restrict__ Wv, const float* __restrict__ bv)
{
    const int op = blockIdx.z;
    const float* X    = (op == 0) ? Xq : (op == 1) ? Xk : Xv;
    const float* W    = (op == 0) ? Wq : (op == 1) ? Wk : Wv;
    const float* bias = (op == 0) ? bq : (op == 1) ? bk : bv;
    float* P = g_P[op];

    __shared__ __align__(16) float As[16][64];
    __shared__ __align__(16) float Ws[16][64];

    const int tid = threadIdx.x;
    const int m0 = blockIdx.y * 64;
    const int n0 = blockIdx.x * 64;
    const int lr = tid >> 2;          // 0..63
    const int lc = (tid & 3) * 4;     // 0,4,8,12
    const int ty = tid >> 4;          // 0..15
    const int tx = tid & 15;          // 0..15

    float acc[4][4] = {};

    for (int k0 = 0; k0 < Dc; k0 += 16) {
        float4 a = *(const float4*)&X[(size_t)(m0 + lr) * Dc + k0 + lc];
        float4 w = *(const float4*)&W[(size_t)(n0 + lr) * Dc + k0 + lc];
        __syncthreads();
        As[lc + 0][lr] = a.x; As[lc + 1][lr] = a.y; As[lc + 2][lr] = a.z; As[lc + 3][lr] = a.w;
        Ws[lc + 0][lr] = w.x; Ws[lc + 1][lr] = w.y; Ws[lc + 2][lr] = w.z; Ws[lc + 3][lr] = w.w;
        __syncthreads();
#pragma unroll
        for (int kk = 0; kk < 16; kk++) {
            float4 av = *(const float4*)&As[kk][ty * 4];
            float4 wv = *(const float4*)&Ws[kk][tx * 4];
            acc[0][0] += av.x * wv.x; acc[0][1] += av.x * wv.y; acc[0][2] += av.x * wv.z; acc[0][3] += av.x * wv.w;
            acc[1][0] += av.y * wv.x; acc[1][1] += av.y * wv.y; acc[1][2] += av.y * wv.z; acc[1][3] += av.y * wv.w;
            acc[2][0] += av.z * wv.x; acc[2][1] += av.z * wv.y; acc[2][2] += av.z * wv.z; acc[2][3] += av.z * wv.w;
            acc[3][0] += av.w * wv.x; acc[3][1] += av.w * wv.y; acc[3][2] += av.w * wv.z; acc[3][3] += av.w * wv.w;
        }
    }
#pragma unroll
    for (int i = 0; i < 4; i++) {
        size_t row = (size_t)(m0 + ty * 4 + i) * Dc + n0 + tx * 4;
#pragma unroll
        for (int j = 0; j < 4; j++)
            P[row + j] = acc[i][j] + bias[n0 + tx * 4 + j];
    }
}

// ============================================================================
// Kernel 2: per-head LayerNorm (k,v) + pos-concat -> QC/KC/VC  (warp per row)
// ============================================================================
__device__ __forceinline__ void warp_red2(float& s, float& sq)
{
#pragma unroll
    for (int off = 16; off; off >>= 1) {
        s  += __shfl_xor_sync(0xffffffffu, s,  off);
        sq += __shfl_xor_sync(0xffffffffu, sq, off);
    }
}

__global__ void ln_concat(const float* __restrict__ pos,
                          const float* __restrict__ gK, const float* __restrict__ betaK,
                          const float* __restrict__ gV, const float* __restrict__ betaV)
{
    const int gwarp = (blockIdx.x * blockDim.x + threadIdx.x) >> 5;
    const int lane = threadIdx.x & 31;
    if (gwarp >= Bc * Lc * Hc) return;
    const int h  = gwarp % Hc;
    const int bl = gwarp / Hc;

    const size_t inbase  = (size_t)bl * Dc + h * DKc;
    const size_t outbase = (size_t)bl * FP + h * Ec;
    const float pv = pos[bl];

    // ---- q: plain concat ----
    {
        float q0 = g_P[0][inbase + lane];
        float q1 = g_P[0][inbase + 32 + lane];
        if (lane == 0) g_QC[outbase] = pv;
        g_QC[outbase + 1 + lane] = q0;
        g_QC[outbase + 1 + 32 + lane] = q1;
    }
    // ---- k: LN + concat ----
    {
        float x0 = g_P[1][inbase + lane];
        float x1 = g_P[1][inbase + 32 + lane];
        float s = x0 + x1, sq = x0 * x0 + x1 * x1;
        warp_red2(s, sq);
        float mean = s * (1.0f / 64.0f);
        float var = sq * (1.0f / 64.0f) - mean * mean;
        float r = rsqrtf(var + 1e-5f);
        float y0 = (x0 - mean) * r * gK[h * DKc + lane] + betaK[h * DKc + lane];
        float y1 = (x1 - mean) * r * gK[h * DKc + 32 + lane] + betaK[h * DKc + 32 + lane];
        if (lane == 0) g_KC[outbase] = pv;
        g_KC[outbase + 1 + lane] = y0;
        g_KC[outbase + 1 + 32 + lane] = y1;
    }
    // ---- v: LN + concat ----
    {
        float x0 = g_P[2][inbase + lane];
        float x1 = g_P[2][inbase + 32 + lane];
        float s = x0 + x1, sq = x0 * x0 + x1 * x1;
        warp_red2(s, sq);
        float mean = s * (1.0f / 64.0f);
        float var = sq * (1.0f / 64.0f) - mean * mean;
        float r = rsqrtf(var + 1e-5f);
        float y0 = (x0 - mean) * r * gV[h * DKc + lane] + betaV[h * DKc + lane];
        float y1 = (x1 - mean) * r * gV[h * DKc + 32 + lane] + betaV[h * DKc + 32 + lane];
        if (lane == 0) g_VC[outbase] = pv;
        g_VC[outbase + 1 + lane] = y0;
        g_VC[outbase + 1 + 32 + lane] = y1;
    }
    // ---- zero the pad columns [Fc, FP) once per row ----
    if (h == 0 && lane < (FP - Fc)) {
        g_QC[(size_t)bl * FP + Fc + lane] = 0.0f;
        g_KC[(size_t)bl * FP + Fc + lane] = 0.0f;
        g_VC[(size_t)bl * FP + Fc + lane] = 0.0f;
    }
}

// ============================================================================
// Kernel 3: attn partials  part[b,h,s] = K_chunk^T @ V_chunk   (deterministic)
// grid: (NSPLIT, H, B), 256 threads (16x16), 5x5 micro-tile over 65x65
// ============================================================================
__global__ void attn_partial()
{
    const int split = blockIdx.x, h = blockIdx.y, b = blockIdx.z;
    __shared__ float ks[8][Ec];
    __shared__ float vs[8][Ec];
    const int tid = threadIdx.x;
    const int td = tid >> 4;   // 0..15
    const int te = tid & 15;   // 0..15

    float acc[5][5] = {};
    const size_t base = ((size_t)b * Lc + (size_t)split * LCHUNK) * FP + h * Ec;

    for (int l0 = 0; l0 < LCHUNK; l0 += 8) {
        __syncthreads();
        for (int idx = tid; idx < 8 * Ec; idx += 256) {
            int r = idx / Ec, c = idx % Ec;
            size_t off = base + (size_t)(l0 + r) * FP + c;
            ks[r][c] = g_KC[off];
            vs[r][c] = g_VC[off];
        }
        __syncthreads();
#pragma unroll
        for (int r = 0; r < 8; r++) {
            float kv[5], vv[5];
#pragma unroll
            for (int i = 0; i < 5; i++) { int d = td + 16 * i; kv[i] = (d < Ec) ? ks[r][d] : 0.0f; }
#pragma unroll
            for (int j = 0; j < 5; j++) { int e = te + 16 * j; vv[j] = (e < Ec) ? vs[r][e] : 0.0f; }
#pragma unroll
            for (int i = 0; i < 5; i++)
#pragma unroll
                for (int j = 0; j < 5; j++)
                    acc[i][j] += kv[i] * vv[j];
        }
    }

    float* out = &g_part[(((size_t)b * Hc + h) * NSPLIT + split) * Ec * Ec];
#pragma unroll
    for (int i = 0; i < 5; i++) {
        int d = td + 16 * i;
        if (d >= Ec) continue;
#pragma unroll
        for (int j = 0; j < 5; j++) {
            int e = te + 16 * j;
            if (e < Ec) out[d * Ec + e] = acc[i][j];
        }
    }
}

// ============================================================================
// Kernel 4: reduce partials, scale by 1/L, write attn output
// ============================================================================
__global__ void attn_reduce(float* __restrict__ attn_out)
{
    const size_t idx = (size_t)blockIdx.x * blockDim.x + threadIdx.x;
    if (idx >= ATTN_ELEMS) return;
    const size_t bh = idx / (Ec * Ec);
    const size_t de = idx % (Ec * Ec);
    float s = 0.0f;
#pragma unroll
    for (int sp = 0; sp < NSPLIT; sp++)
        s += g_part[(bh * NSPLIT + sp) * (Ec * Ec) + de];
    attn_out[idx] = s * (1.0f / (float)Lc);
}

// ============================================================================
// Kernel 5: fold attn into fcW:  W2[b, h*65+d, o] = sum_e attn[b,h,d,e]*fcW[o, h*65+e]
// grid: (FP, B), 256 threads
// ============================================================================
__global__ void w2_kernel(const float* __restrict__ attn, const float* __restrict__ fcW)
{
    const int f = blockIdx.x;
    const int b = blockIdx.y;
    const int tid = threadIdx.x;
    float* out = &g_W2[((size_t)b * FP + f) * Dc];
    if (f >= Fc) {
        for (int o = tid; o < Dc; o += 256) out[o] = 0.0f;
        return;
    }
    const int h = f / Ec, d = f % Ec;
    __shared__ float arow[Ec];
    if (tid < Ec) arow[tid] = attn[(((size_t)b * Hc + h) * Ec + d) * Ec + tid];
    __syncthreads();
    for (int o = tid; o < Dc; o += 256) {
        const float* wrow = &fcW[(size_t)o * Fc + h * Ec];
        float s = 0.0f;
#pragma unroll
        for (int e = 0; e < Ec; e++) s += arow[e] * wrow[e];
        out[o] = s;
    }
}

// ============================================================================
// Kernel 6: att_output[b] = QC[b] @ W2[b] + fcb   ("NN" SGEMM, K=528)
// grid: (Dc/64, Lc/64, B)
// ============================================================================
__global__ void out_gemm(const float* __restrict__ fcb, float* __restrict__ out)
{
    const int b = blockIdx.z;
    const float* A  = &g_QC[(size_t)b * Lc * FP];
    const float* Bm = &g_W2[(size_t)b * FP * Dc];
    float* C = &out[(size_t)b * Lc * Dc];

    __shared__ __align__(16) float As[16][64];
    __shared__ __align__(16) float Ws[16][64];

    const int tid = threadIdx.x;
    const int m0 = blockIdx.y * 64;
    const int n0 = blockIdx.x * 64;
    const int lr = tid >> 2;
    const int lc = (tid & 3) * 4;
    const int wr = tid >> 4;            // 0..15 (B-tile row)
    const int wc = (tid & 15) * 4;      // 0..60 (B-tile col)
    const int ty = tid >> 4;
    const int tx = tid & 15;

    float acc[4][4] = {};

    for (int k0 = 0; k0 < FP; k0 += 16) {
        float4 a = *(const float4*)&A[(size_t)(m0 + lr) * FP + k0 + lc];
        float4 w = *(const float4*)&Bm[(size_t)(k0 + wr) * Dc + n0 + wc];
        __syncthreads();
        As[lc + 0][lr] = a.x; As[lc + 1][lr] = a.y; As[lc + 2][lr] = a.z; As[lc + 3][lr] = a.w;
        *(float4*)&Ws[wr][wc] = w;
        __syncthreads();
#pragma unroll
        for (int kk = 0; kk < 16; kk++) {
            float4 av = *(const float4*)&As[kk][ty * 4];
            float4 wv = *(const float4*)&Ws[kk][tx * 4];
            acc[0][0] += av.x * wv.x; acc[0][1] += av.x * wv.y; acc[0][2] += av.x * wv.z; acc[0][3] += av.x * wv.w;
            acc[1][0] += av.y * wv.x; acc[1][1] += av.y * wv.y; acc[1][2] += av.y * wv.z; acc[1][3] += av.y * wv.w;
            acc[2][0] += av.z * wv.x; acc[2][1] += av.z * wv.y; acc[2][2] += av.z * wv.z; acc[2][3] += av.z * wv.w;
            acc[3][0] += av.w * wv.x; acc[3][1] += av.w * wv.y; acc[3][2] += av.w * wv.z; acc[3][3] += av.w * wv.w;
        }
    }
#pragma unroll
    for (int i = 0; i < 4; i++) {
        size_t row = (size_t)(m0 + ty * 4 + i) * Dc + n0 + tx * 4;
#pragma unroll
        for (int j = 0; j < 4; j++)
            C[row + j] = acc[i][j] + fcb[n0 + tx * 4 + j];
    }
}

// ============================================================================
// launch
// ============================================================================
extern "C" void kernel_launch(void* const* d_in, const int* in_sizes, int n_in,
                              void* d_out, int out_size)
{
    const float* query = (const float*)d_in[0];
    const float* key   = (const float*)d_in[1];
    const float* value = (const float*)d_in[2];
    const float* pos   = (const float*)d_in[3];
    const float* Wq    = (const float*)d_in[4];
    const float* bq    = (const float*)d_in[5];
    const float* Wk    = (const float*)d_in[6];
    const float* bk    = (const float*)d_in[7];
    const float* Wv    = (const float*)d_in[8];
    const float* bv    = (const float*)d_in[9];
    const float* gK    = (const float*)d_in[10];
    const float* betaK = (const float*)d_in[11];
    const float* gV    = (const float*)d_in[12];
    const float* betaV = (const float*)d_in[13];
    const float* fcW   = (const float*)d_in[14];
    const float* fcb   = (const float*)d_in[15];

    float* att_out  = (float*)d_out;                 // [B, L, D]
    float* attn_out = att_out + ATT_ELEMS;           // [B, H, E, E]

    // 1) three projections
    proj_gemm<<<dim3(Dc / 64, (Bc * Lc) / 64, 3), 256>>>(query, key, value,
                                                          Wq, bq, Wk, bk, Wv, bv);
    // 2) per-head LN + pos concat
    ln_concat<<<(Bc * Lc * Hc) / 8, 256>>>(pos, gK, betaK, gV, betaV);
    // 3) attn partials (deterministic split over L)
    attn_partial<<<dim3(NSPLIT, Hc, Bc), 256>>>();
    // 4) reduce + scale -> attn output
    attn_reduce<<<(unsigned)((ATTN_ELEMS + 255) / 256), 256>>>(attn_out);
    // 5) fold attn into fc weights
    w2_kernel<<<dim3(FP, Bc), 256>>>(attn_out, fcW);
    // 6) fused out-projection GEMM
    out_gemm<<<dim3(Dc / 64, Lc / 64, Bc), 256>>>(fcb, att_out);
}

// round 3
// speedup vs baseline: 2.0408x; 2.0408x over previous
#include <cuda_runtime.h>
#include <cstdint>

// ---------------- problem constants ----------------
#define Bc 4
#define Lc 8192
#define Dc 512
#define Hc 8
#define DKc 64
#define Ec 65           // DK + PD
#define Fc 520          // H * E
#define FP 544          // padded F (multiple of 32)
#define NSPLIT 16
#define LCHUNK (Lc / NSPLIT)

#define ATT_ELEMS  ((size_t)Bc * Lc * Dc)
#define ATTN_ELEMS ((size_t)Bc * Hc * Ec * Ec)

// ---------------- scratch (device globals; no allocs allowed) ----------------
__device__ float g_P[3][(size_t)Bc * Lc * Dc];   // q/k/v projections
__device__ float g_QC[(size_t)Bc * Lc * FP];     // concat q (padded, zeros in pad)
__device__ float g_KC[(size_t)Bc * Lc * FP];     // concat k (LN'd)
__device__ float g_VC[(size_t)Bc * Lc * FP];     // concat v (LN'd)
__device__ float g_part[(size_t)Bc * Hc * NSPLIT * Ec * Ec];
__device__ float g_W2T[(size_t)Bc * Dc * FP];    // attn folded into fcW, transposed [b][o][f]

// ============================================================================
// tf32 helpers
// ============================================================================
__device__ __forceinline__ uint32_t f2tf32(float x) {
    uint32_t r;
    asm("cvt.rna.tf32.f32 %0, %1;" : "=r"(r) : "f"(x));
    return r;
}

__device__ __forceinline__ void mma_tf32(float c[4], const uint32_t a[4], const uint32_t b[2]) {
    asm volatile(
        "mma.sync.aligned.m16n8k8.row.col.f32.tf32.tf32.f32 "
        "{%0,%1,%2,%3}, {%4,%5,%6,%7}, {%8,%9}, {%0,%1,%2,%3};"
        : "+f"(c[0]), "+f"(c[1]), "+f"(c[2]), "+f"(c[3])
        : "r"(a[0]), "r"(a[1]), "r"(a[2]), "r"(a[3]), "r"(b[0]), "r"(b[1]));
}

// ============================================================================
// tf32 mma.sync GEMM:  C[M,N] = A[M,K] @ B[N,K]^T + bias   (both K-major fp32)
// CTA tile 128x128, K-block 32, 8 warps each 64x32, double-buffered SMEM.
// grid: (N/128, M/128)
// ============================================================================
#define LDS_STRIDE 36                         // floats; (4g+t) mod 32 conflict-free
#define TILE_FLOATS (128 * LDS_STRIDE)        // 4608 floats per operand tile
#define STAGE_BYTES (2 * TILE_FLOATS * 4)     // A + B = 36864 B
#define SMEM_GEMM (2 * STAGE_BYTES)           // 73728 B

__global__ void __launch_bounds__(256)
gemm_mma(const float* __restrict__ A, const float* __restrict__ Bw,
         const float* __restrict__ bias, float* __restrict__ C,
         int lda, int ldc, int K)
{
    extern __shared__ __align__(16) uint32_t smem[];
    const int tid = threadIdx.x;
    const int wid = tid >> 5;
    const int lane = tid & 31;
    const int g = lane >> 2;       // group 0..7
    const int t = lane & 3;        // 0..3
    const int mw = (wid >> 2) * 64;   // warp m offset in tile
    const int nw = (wid & 3) * 32;    // warp n offset in tile

    const int m0 = blockIdx.y * 128;
    const int n0 = blockIdx.x * 128;
    const int NKB = K >> 5;

    // loader mapping: each thread handles 1 row, 16 cols (half of kblock)
    const int lrow = tid >> 1;
    const int lcol = (tid & 1) << 4;

    float acc[4][4][4] = {};
    float4 a4[4], b4[4];

    // ---- prologue: LDG tile 0 ----
    {
        const float* ap = A + (size_t)(m0 + lrow) * lda + lcol;
        const float* bp = Bw + (size_t)(n0 + lrow) * lda + lcol;
#pragma unroll
        for (int i = 0; i < 4; i++) {
            a4[i] = *(const float4*)(ap + 4 * i);
            b4[i] = *(const float4*)(bp + 4 * i);
        }
    }

#pragma unroll 1
    for (int kb = 0; kb < NKB; kb++) {
        const int cur = kb & 1;
        uint32_t* As = smem + cur * (2 * TILE_FLOATS);
        uint32_t* Bs = As + TILE_FLOATS;

        // STS current staged registers (tf32-converted)
        {
            uint32_t* ad = As + lrow * LDS_STRIDE + lcol;
            uint32_t* bd = Bs + lrow * LDS_STRIDE + lcol;
#pragma unroll
            for (int i = 0; i < 4; i++) {
                uint4 ua, ub;
                ua.x = f2tf32(a4[i].x); ua.y = f2tf32(a4[i].y);
                ua.z = f2tf32(a4[i].z); ua.w = f2tf32(a4[i].w);
                ub.x = f2tf32(b4[i].x); ub.y = f2tf32(b4[i].y);
                ub.z = f2tf32(b4[i].z); ub.w = f2tf32(b4[i].w);
                *(uint4*)(ad + 4 * i) = ua;
                *(uint4*)(bd + 4 * i) = ub;
            }
        }
        __syncthreads();

        // LDG next tile while computing this one
        if (kb + 1 < NKB) {
            const int k0 = (kb + 1) << 5;
            const float* ap = A + (size_t)(m0 + lrow) * lda + k0 + lcol;
            const float* bp = Bw + (size_t)(n0 + lrow) * lda + k0 + lcol;
#pragma unroll
            for (int i = 0; i < 4; i++) {
                a4[i] = *(const float4*)(ap + 4 * i);
                b4[i] = *(const float4*)(bp + 4 * i);
            }
        }

        // compute: 4 k8 steps
#pragma unroll
        for (int kk = 0; kk < 32; kk += 8) {
            uint32_t af[4][4];
#pragma unroll
            for (int i = 0; i < 4; i++) {
                const uint32_t* base = As + (mw + 16 * i) * LDS_STRIDE + kk;
                af[i][0] = base[(g)     * LDS_STRIDE + t];
                af[i][1] = base[(g + 8) * LDS_STRIDE + t];
                af[i][2] = base[(g)     * LDS_STRIDE + t + 4];
                af[i][3] = base[(g + 8) * LDS_STRIDE + t + 4];
            }
            uint32_t bf[4][2];
#pragma unroll
            for (int j = 0; j < 4; j++) {
                const uint32_t* base = Bs + (nw + 8 * j + g) * LDS_STRIDE + kk;
                bf[j][0] = base[t];
                bf[j][1] = base[t + 4];
            }
#pragma unroll
            for (int i = 0; i < 4; i++)
#pragma unroll
                for (int j = 0; j < 4; j++)
                    mma_tf32(acc[i][j], af[i], bf[j]);
        }
        __syncthreads();
    }

    // ---- epilogue: add bias, store ----
#pragma unroll
    for (int i = 0; i < 4; i++) {
        const int row0 = m0 + mw + 16 * i + g;
#pragma unroll
        for (int j = 0; j < 4; j++) {
            const int col = n0 + nw + 8 * j + 2 * t;
            float2 bv = *(const float2*)(bias + col);
            float2 o0, o1;
            o0.x = acc[i][j][0] + bv.x;  o0.y = acc[i][j][1] + bv.y;
            o1.x = acc[i][j][2] + bv.x;  o1.y = acc[i][j][3] + bv.y;
            *(float2*)(C + (size_t)row0 * ldc + col) = o0;
            *(float2*)(C + (size_t)(row0 + 8) * ldc + col) = o1;
        }
    }
}

// ============================================================================
// per-head LayerNorm (k,v) + pos-concat -> QC/KC/VC  (warp per (b,l,h) row)
// ============================================================================
__device__ __forceinline__ void warp_red2(float& s, float& sq)
{
#pragma unroll
    for (int off = 16; off; off >>= 1) {
        s  += __shfl_xor_sync(0xffffffffu, s,  off);
        sq += __shfl_xor_sync(0xffffffffu, sq, off);
    }
}

__global__ void ln_concat(const float* __restrict__ pos,
                          const float* __restrict__ gK, const float* __restrict__ betaK,
                          const float* __restrict__ gV, const float* __restrict__ betaV)
{
    const int gwarp = (blockIdx.x * blockDim.x + threadIdx.x) >> 5;
    const int lane = threadIdx.x & 31;
    if (gwarp >= Bc * Lc * Hc) return;
    const int h  = gwarp % Hc;
    const int bl = gwarp / Hc;

    const size_t inbase  = (size_t)bl * Dc + h * DKc;
    const size_t outbase = (size_t)bl * FP + h * Ec;
    const float pv = pos[bl];

    {   // q: plain concat
        float q0 = g_P[0][inbase + lane];
        float q1 = g_P[0][inbase + 32 + lane];
        if (lane == 0) g_QC[outbase] = pv;
        g_QC[outbase + 1 + lane] = q0;
        g_QC[outbase + 1 + 32 + lane] = q1;
    }
    {   // k: LN + concat
        float x0 = g_P[1][inbase + lane];
        float x1 = g_P[1][inbase + 32 + lane];
        float s = x0 + x1, sq = x0 * x0 + x1 * x1;
        warp_red2(s, sq);
        float mean = s * (1.0f / 64.0f);
        float var = sq * (1.0f / 64.0f) - mean * mean;
        float r = rsqrtf(var + 1e-5f);
        float y0 = (x0 - mean) * r * gK[h * DKc + lane] + betaK[h * DKc + lane];
        float y1 = (x1 - mean) * r * gK[h * DKc + 32 + lane] + betaK[h * DKc + 32 + lane];
        if (lane == 0) g_KC[outbase] = pv;
        g_KC[outbase + 1 + lane] = y0;
        g_KC[outbase + 1 + 32 + lane] = y1;
    }
    {   // v: LN + concat
        float x0 = g_P[2][inbase + lane];
        float x1 = g_P[2][inbase + 32 + lane];
        float s = x0 + x1, sq = x0 * x0 + x1 * x1;
        warp_red2(s, sq);
        float mean = s * (1.0f / 64.0f);
        float var = sq * (1.0f / 64.0f) - mean * mean;
        float r = rsqrtf(var + 1e-5f);
        float y0 = (x0 - mean) * r * gV[h * DKc + lane] + betaV[h * DKc + lane];
        float y1 = (x1 - mean) * r * gV[h * DKc + 32 + lane] + betaV[h * DKc + 32 + lane];
        if (lane == 0) g_VC[outbase] = pv;
        g_VC[outbase + 1 + lane] = y0;
        g_VC[outbase + 1 + 32 + lane] = y1;
    }
    // zero pad cols [Fc, FP)
    if (h == 0 && lane < (FP - Fc)) {
        g_QC[(size_t)bl * FP + Fc + lane] = 0.0f;
        g_KC[(size_t)bl * FP + Fc + lane] = 0.0f;
        g_VC[(size_t)bl * FP + Fc + lane] = 0.0f;
    }
}

// ============================================================================
// attn partials:  part[b,h,s] = K_chunk^T @ V_chunk  (fp32, deterministic)
// ============================================================================
__global__ void attn_partial()
{
    const int split = blockIdx.x, h = blockIdx.y, b = blockIdx.z;
    __shared__ float ks[8][Ec];
    __shared__ float vs[8][Ec];
    const int tid = threadIdx.x;
    const int td = tid >> 4;
    const int te = tid & 15;

    float acc[5][5] = {};
    const size_t base = ((size_t)b * Lc + (size_t)split * LCHUNK) * FP + h * Ec;

    for (int l0 = 0; l0 < LCHUNK; l0 += 8) {
        __syncthreads();
        for (int idx = tid; idx < 8 * Ec; idx += 256) {
            int r = idx / Ec, cc = idx % Ec;
            size_t off = base + (size_t)(l0 + r) * FP + cc;
            ks[r][cc] = g_KC[off];
            vs[r][cc] = g_VC[off];
        }
        __syncthreads();
#pragma unroll
        for (int r = 0; r < 8; r++) {
            float kv[5], vv[5];
#pragma unroll
            for (int i = 0; i < 5; i++) { int d = td + 16 * i; kv[i] = (d < Ec) ? ks[r][d] : 0.0f; }
#pragma unroll
            for (int j = 0; j < 5; j++) { int e = te + 16 * j; vv[j] = (e < Ec) ? vs[r][e] : 0.0f; }
#pragma unroll
            for (int i = 0; i < 5; i++)
#pragma unroll
                for (int j = 0; j < 5; j++)
                    acc[i][j] += kv[i] * vv[j];
        }
    }

    float* out = &g_part[(((size_t)b * Hc + h) * NSPLIT + split) * Ec * Ec];
#pragma unroll
    for (int i = 0; i < 5; i++) {
        int d = td + 16 * i;
        if (d >= Ec) continue;
#pragma unroll
        for (int j = 0; j < 5; j++) {
            int e = te + 16 * j;
            if (e < Ec) out[d * Ec + e] = acc[i][j];
        }
    }
}

// ============================================================================
// reduce partials, scale by 1/L -> attn output
// ============================================================================
__global__ void attn_reduce(float* __restrict__ attn_out)
{
    const size_t idx = (size_t)blockIdx.x * blockDim.x + threadIdx.x;
    if (idx >= ATTN_ELEMS) return;
    const size_t bh = idx / (Ec * Ec);
    const size_t de = idx % (Ec * Ec);
    float s = 0.0f;
#pragma unroll
    for (int sp = 0; sp < NSPLIT; sp++)
        s += g_part[(bh * NSPLIT + sp) * (Ec * Ec) + de];
    attn_out[idx] = s * (1.0f / (float)Lc);
}

// ============================================================================
// fold attn into fcW, transposed:  W2T[b,o,h*65+d] = sum_e attn[b,h,d,e]*fcW[o,h*65+e]
// ============================================================================
__global__ void w2t_kernel(const float* __restrict__ attn, const float* __restrict__ fcW)
{
    const int bh = blockIdx.x;
    const int b = bh >> 3, h = bh & 7;
    __shared__ float a[Ec * Ec];
    const int tid = threadIdx.x;
    for (int i = tid; i < Ec * Ec; i += 256)
        a[i] = attn[(size_t)bh * Ec * Ec + i];
    __syncthreads();

    for (int o = tid; o < Dc; o += 256) {
        float w[Ec];
        const float* wr = &fcW[(size_t)o * Fc + h * Ec];
#pragma unroll
        for (int e = 0; e < Ec; e++) w[e] = wr[e];
        float* out = &g_W2T[((size_t)b * Dc + o) * FP + h * Ec];
#pragma unroll 1
        for (int d0 = 0; d0 < Ec; d0 += 5) {
            float s0 = 0, s1 = 0, s2 = 0, s3 = 0, s4 = 0;
#pragma unroll
            for (int e = 0; e < Ec; e++) {
                float we = w[e];
                s0 += a[(d0 + 0) * Ec + e] * we;
                s1 += a[(d0 + 1) * Ec + e] * we;
                s2 += a[(d0 + 2) * Ec + e] * we;
                s3 += a[(d0 + 3) * Ec + e] * we;
                s4 += a[(d0 + 4) * Ec + e] * we;
            }
            out[d0 + 0] = s0; out[d0 + 1] = s1; out[d0 + 2] = s2;
            out[d0 + 3] = s3; out[d0 + 4] = s4;
        }
    }
    // zero pad cols [Fc, FP)
    if (h == 0) {
        for (int i = tid; i < Dc * (FP - Fc); i += 256) {
            int o = i / (FP - Fc), cc = Fc + i % (FP - Fc);
            g_W2T[((size_t)b * Dc + o) * FP + cc] = 0.0f;
        }
    }
}

// ============================================================================
// launch
// ============================================================================
extern "C" void kernel_launch(void* const* d_in, const int* in_sizes, int n_in,
                              void* d_out, int out_size)
{
    const float* query = (const float*)d_in[0];
    const float* key   = (const float*)d_in[1];
    const float* value = (const float*)d_in[2];
    const float* pos   = (const float*)d_in[3];
    const float* Wq    = (const float*)d_in[4];
    const float* bq    = (const float*)d_in[5];
    const float* Wk    = (const float*)d_in[6];
    const float* bk    = (const float*)d_in[7];
    const float* Wv    = (const float*)d_in[8];
    const float* bv    = (const float*)d_in[9];
    const float* gK    = (const float*)d_in[10];
    const float* betaK = (const float*)d_in[11];
    const float* gV    = (const float*)d_in[12];
    const float* betaV = (const float*)d_in[13];
    const float* fcW   = (const float*)d_in[14];
    const float* fcb   = (const float*)d_in[15];

    float* att_out  = (float*)d_out;
    float* attn_out = att_out + ATT_ELEMS;

    float *pP = nullptr, *pQC = nullptr, *pW2T = nullptr;
    cudaGetSymbolAddress((void**)&pP, g_P);
    cudaGetSymbolAddress((void**)&pQC, g_QC);
    cudaGetSymbolAddress((void**)&pW2T, g_W2T);

    cudaFuncSetAttribute(gemm_mma, cudaFuncAttributeMaxDynamicSharedMemorySize, SMEM_GEMM);

    const size_t PSTRIDE = (size_t)Bc * Lc * Dc;

    // 1) three projections: P[op] = X @ W^T + b   (M=32768, N=512, K=512)
    gemm_mma<<<dim3(4, 256), 256, SMEM_GEMM>>>(query, Wq, bq, pP + 0 * PSTRIDE, Dc, Dc, Dc);
    gemm_mma<<<dim3(4, 256), 256, SMEM_GEMM>>>(key,   Wk, bk, pP + 1 * PSTRIDE, Dc, Dc, Dc);
    gemm_mma<<<dim3(4, 256), 256, SMEM_GEMM>>>(value, Wv, bv, pP + 2 * PSTRIDE, Dc, Dc, Dc);

    // 2) per-head LN + pos concat
    ln_concat<<<(Bc * Lc * Hc) / 8, 256>>>(pos, gK, betaK, gV, betaV);

    // 3) attn partials (deterministic split over L, fp32 exact)
    attn_partial<<<dim3(NSPLIT, Hc, Bc), 256>>>();

    // 4) reduce + scale -> attn output
    attn_reduce<<<(unsigned)((ATTN_ELEMS + 255) / 256), 256>>>(attn_out);

    // 5) fold attn into fc weights (transposed, K-major)
    w2t_kernel<<<Bc * Hc, 256>>>(attn_out, fcW);

    // 6) output GEMM per batch: att[b] = QC[b] @ W2T[b]^T + fcb  (M=8192, N=512, K=544)
    for (int b = 0; b < Bc; b++) {
        gemm_mma<<<dim3(4, 64), 256, SMEM_GEMM>>>(pQC + (size_t)b * Lc * FP,
                                                   pW2T + (size_t)b * Dc * FP,
                                                   fcb,
                                                   att_out + (size_t)b * Lc * Dc,
                                                   FP, Dc, FP);
    }
}

// round 4
// speedup vs baseline: 2.3017x; 1.1278x over previous
#include <cuda_runtime.h>
#include <cstdint>

// ---------------- problem constants ----------------
#define Bc 4
#define Lc 8192
#define Dc 512
#define Hc 8
#define DKc 64
#define Ec 65           // DK + PD
#define Fc 520          // H * E
#define FP 544          // padded F (multiple of 32)
#define EH 68           // padded per-head width for KH/VH (16B aligned)
#define NSPLIT 16
#define LCHUNK (Lc / NSPLIT)

#define ATT_ELEMS  ((size_t)Bc * Lc * Dc)
#define ATTN_ELEMS ((size_t)Bc * Hc * Ec * Ec)

// ---------------- scratch (device globals; no allocs allowed) ----------------
__device__ float g_QC[(size_t)Bc * Lc * FP];        // concat q [bl][FP], pad zeroed
__device__ float g_KH[(size_t)Bc * Hc * Lc * EH];   // LN'd k, head-major [b,h,l,68]
__device__ float g_VH[(size_t)Bc * Hc * Lc * EH];   // LN'd v, head-major
__device__ float g_part[(size_t)Bc * Hc * NSPLIT * Ec * Ec];
__device__ float g_W2T[(size_t)Bc * Dc * FP];       // attn folded into fcW, [b][o][f]

// ============================================================================
// helpers
// ============================================================================
__device__ __forceinline__ uint32_t smem_u32(const void* p) {
    uint32_t a;
    asm("{ .reg .u64 t; cvta.to.shared.u64 t, %1; cvt.u32.u64 %0, t; }" : "=r"(a) : "l"(p));
    return a;
}
__device__ __forceinline__ uint32_t f2tf32(float x) {
    uint32_t r;
    asm("cvt.rna.tf32.f32 %0, %1;" : "=r"(r) : "f"(x));
    return r;
}
__device__ __forceinline__ void cp16(uint32_t dst, const float* src) {
    asm volatile("cp.async.ca.shared.global [%0], [%1], 16;" :: "r"(dst), "l"(src));
}
#define CP_COMMIT() asm volatile("cp.async.commit_group;" ::: "memory")
#define CP_WAIT0()  asm volatile("cp.async.wait_group 0;" ::: "memory")
#define CP_WAIT1()  asm volatile("cp.async.wait_group 1;" ::: "memory")

__device__ __forceinline__ void mma_tf32(float c[4], const uint32_t a[4], const uint32_t b[2]) {
    asm volatile(
        "mma.sync.aligned.m16n8k8.row.col.f32.tf32.tf32.f32 "
        "{%0,%1,%2,%3}, {%4,%5,%6,%7}, {%8,%9}, {%0,%1,%2,%3};"
        : "+f"(c[0]), "+f"(c[1]), "+f"(c[2]), "+f"(c[3])
        : "r"(a[0]), "r"(a[1]), "r"(a[2]), "r"(a[3]), "r"(b[0]), "r"(b[1]));
}

// ============================================================================
// shared GEMM mainloop: acc[4][4][4] += A[m0..+128, :K] @ B[n0..+128, :K]^T
// 128x128 tile, K-block 32, cp.async 3-stage, tf32 cvt in consumer.
// ============================================================================
#define SSTR 36                        // smem row stride (floats), conflict-free
#define ATILE (128 * SSTR)             // 4608 floats per operand per stage
#define STAGEF (2 * ATILE)             // 9216 floats per stage
#define NSTAGE 3
#define SMEM_GEMM (NSTAGE * STAGEF * 4)   // 110592 bytes

__device__ __forceinline__ void gemm_mainloop(
    const float* __restrict__ A, const float* __restrict__ Bw,
    int lda, int NKB, int m0, int n0,
    float* smf, uint32_t sbase, float acc[4][4][4])
{
    const int tid = threadIdx.x;
    const int wid = tid >> 5;
    const int lane = tid & 31;
    const int g = lane >> 2;
    const int t = lane & 3;
    const int mw = (wid >> 2) * 64;
    const int nw = (wid & 3) * 32;

    const int crow = tid >> 1;            // copy row 0..127
    const int ccol = (tid & 1) << 4;      // 0 or 16 floats

    // prologue: stages 0,1
#pragma unroll
    for (int s = 0; s < 2; s++) {
        const int k0 = s << 5;
        uint32_t as = sbase + (uint32_t)(s * STAGEF) * 4u;
        uint32_t bs = as + (uint32_t)ATILE * 4u;
        const float* ap = A + (size_t)(m0 + crow) * lda + k0 + ccol;
        const float* bp = Bw + (size_t)(n0 + crow) * lda + k0 + ccol;
        uint32_t doff = (uint32_t)(crow * SSTR + ccol) * 4u;
#pragma unroll
        for (int i = 0; i < 4; i++) {
            cp16(as + doff + 16u * i, ap + 4 * i);
            cp16(bs + doff + 16u * i, bp + 4 * i);
        }
        CP_COMMIT();
    }

#pragma unroll 1
    for (int kb = 0; kb < NKB; kb++) {
        if (kb == NKB - 1) { CP_WAIT0(); } else { CP_WAIT1(); }
        __syncthreads();

        // issue copy for kb+2
        if (kb + 2 < NKB) {
            const int s = (kb + 2) % NSTAGE;
            const int k0 = (kb + 2) << 5;
            uint32_t as = sbase + (uint32_t)(s * STAGEF) * 4u;
            uint32_t bs = as + (uint32_t)ATILE * 4u;
            const float* ap = A + (size_t)(m0 + crow) * lda + k0 + ccol;
            const float* bp = Bw + (size_t)(n0 + crow) * lda + k0 + ccol;
            uint32_t doff = (uint32_t)(crow * SSTR + ccol) * 4u;
#pragma unroll
            for (int i = 0; i < 4; i++) {
                cp16(as + doff + 16u * i, ap + 4 * i);
                cp16(bs + doff + 16u * i, bp + 4 * i);
            }
        }
        CP_COMMIT();

        // compute stage kb%3
        const float* As = smf + (kb % NSTAGE) * STAGEF;
        const float* Bs = As + ATILE;
#pragma unroll
        for (int kk = 0; kk < 32; kk += 8) {
            uint32_t af[4][4];
#pragma unroll
            for (int i = 0; i < 4; i++) {
                const float* base = As + (mw + 16 * i) * SSTR + kk;
                af[i][0] = f2tf32(base[(g)     * SSTR + t]);
                af[i][1] = f2tf32(base[(g + 8) * SSTR + t]);
                af[i][2] = f2tf32(base[(g)     * SSTR + t + 4]);
                af[i][3] = f2tf32(base[(g + 8) * SSTR + t + 4]);
            }
            uint32_t bf[4][2];
#pragma unroll
            for (int j = 0; j < 4; j++) {
                const float* base = Bs + (nw + 8 * j + g) * SSTR + kk;
                bf[j][0] = f2tf32(base[t]);
                bf[j][1] = f2tf32(base[t + 4]);
            }
#pragma unroll
            for (int i = 0; i < 4; i++)
#pragma unroll
                for (int j = 0; j < 4; j++)
                    mma_tf32(acc[i][j], af[i], bf[j]);
        }
    }
}

// ============================================================================
// Kernel A: fused projection + LN + concat.  grid (4, 256, 3), 256 thr.
// z=0: q -> g_QC (concat, pad);  z=1: k -> g_KH (LN);  z=2: v -> g_VH (LN)
// ============================================================================
#define CSTR 132

__global__ void __launch_bounds__(256)
proj_fused(const float* __restrict__ Xq, const float* __restrict__ Xk,
           const float* __restrict__ Xv,
           const float* __restrict__ Wq, const float* __restrict__ bq,
           const float* __restrict__ Wk, const float* __restrict__ bk,
           const float* __restrict__ Wv, const float* __restrict__ bv,
           const float* __restrict__ gK, const float* __restrict__ betaK,
           const float* __restrict__ gV, const float* __restrict__ betaV,
           const float* __restrict__ pos)
{
    extern __shared__ __align__(16) float smf[];
    const uint32_t sbase = smem_u32(smf);
    const int mode = blockIdx.z;
    const float* A    = (mode == 0) ? Xq : (mode == 1) ? Xk : Xv;
    const float* W    = (mode == 0) ? Wq : (mode == 1) ? Wk : Wv;
    const float* bias = (mode == 0) ? bq : (mode == 1) ? bk : bv;
    const float* gamm = (mode == 1) ? gK : gV;
    const float* beta = (mode == 1) ? betaK : betaV;

    const int m0 = blockIdx.y * 128;
    const int n0 = blockIdx.x * 128;

    float acc[4][4][4] = {};
    gemm_mainloop(A, W, Dc, Dc / 32, m0, n0, smf, sbase, acc);

    // ---- stage tile (+bias) into smem ----
    __syncthreads();
    const int tid = threadIdx.x;
    const int wid = tid >> 5;
    const int lane = tid & 31;
    const int g = lane >> 2;
    const int t = lane & 3;
    const int mw = (wid >> 2) * 64;
    const int nw = (wid & 3) * 32;

#pragma unroll
    for (int i = 0; i < 4; i++) {
        const int r0 = mw + 16 * i + g;
#pragma unroll
        for (int j = 0; j < 4; j++) {
            const int col = nw + 8 * j + 2 * t;
            float2 bv2 = *(const float2*)(bias + n0 + col);
            smf[r0 * CSTR + col]       = acc[i][j][0] + bv2.x;
            smf[r0 * CSTR + col + 1]   = acc[i][j][1] + bv2.y;
            smf[(r0 + 8) * CSTR + col]     = acc[i][j][2] + bv2.x;
            smf[(r0 + 8) * CSTR + col + 1] = acc[i][j][3] + bv2.y;
        }
    }
    __syncthreads();

    // ---- per-row epilogue: 8 warps x 16 rows ----
    for (int rr = 0; rr < 16; rr++) {
        const int r = wid * 16 + rr;
        const int m = m0 + r;                 // = b*L + l
        const int b = m >> 13, l = m & (Lc - 1);
        const float pv = pos[m];
#pragma unroll
        for (int hh = 0; hh < 2; hh++) {
            const int h = (n0 >> 6) + hh;
            float x0 = smf[r * CSTR + 64 * hh + lane];
            float x1 = smf[r * CSTR + 64 * hh + lane + 32];
            if (mode == 0) {
                // q: plain concat into g_QC
                float* qrow = &g_QC[(size_t)m * FP + h * Ec];
                if (lane == 0) qrow[0] = pv;
                qrow[1 + lane] = x0;
                qrow[1 + lane + 32] = x1;
                if (hh == 1 && n0 == 384 && lane < (FP - Fc))
                    g_QC[(size_t)m * FP + Fc + lane] = 0.0f;
            } else {
                // LN over 64 vals (2 per lane)
                float s = x0 + x1, sq = x0 * x0 + x1 * x1;
#pragma unroll
                for (int off = 16; off; off >>= 1) {
                    s  += __shfl_xor_sync(0xffffffffu, s,  off);
                    sq += __shfl_xor_sync(0xffffffffu, sq, off);
                }
                float mean = s * (1.0f / 64.0f);
                float var = sq * (1.0f / 64.0f) - mean * mean;
                float rstd = rsqrtf(var + 1e-5f);
                float y0 = (x0 - mean) * rstd * gamm[h * DKc + lane] + beta[h * DKc + lane];
                float y1 = (x1 - mean) * rstd * gamm[h * DKc + lane + 32] + beta[h * DKc + lane + 32];
                float* orow = ((mode == 1) ? g_KH : g_VH) +
                              (((size_t)b * Hc + h) * Lc + l) * EH;
                if (lane == 0) orow[0] = pv;
                orow[1 + lane] = y0;
                orow[1 + lane + 32] = y1;
                if (lane < 2) orow[66 + lane] = 0.0f;   // pad cols
            }
        }
    }
}

// ============================================================================
// Kernel B: attn partials  part[b,h,s] = K_chunk^T @ V_chunk  (fp32 exact)
// cp.async double-buffered, 16 rows/iter. grid (NSPLIT, H, B), 256 thr.
// ============================================================================
__global__ void __launch_bounds__(256)
attn_partial()
{
    __shared__ __align__(16) float ks[2][16][80];
    __shared__ __align__(16) float vs[2][16][80];
    const int split = blockIdx.x, h = blockIdx.y, b = blockIdx.z;
    const int tid = threadIdx.x;
    const int td = tid >> 4;
    const int te = tid & 15;

    // zero pad columns (and everything else once)
    for (int i = tid; i < 2 * 16 * 80; i += 256) {
        ((float*)ks)[i] = 0.0f;
        ((float*)vs)[i] = 0.0f;
    }
    __syncthreads();

    const float* Kbase = g_KH + (((size_t)b * Hc + h) * Lc + (size_t)split * LCHUNK) * EH;
    const float* Vbase = g_VH + (((size_t)b * Hc + h) * Lc + (size_t)split * LCHUNK) * EH;

    // copy helper: 544 16B chunks (K:272, V:272)
    auto issue = [&](int it) {
        const int buf = it & 1;
        const int l0 = it * 16;
#pragma unroll
        for (int c = 0; c < 3; c++) {
            int idx = tid + c * 256;
            if (idx < 544) {
                int arr = idx >= 272;
                int i2 = arr ? idx - 272 : idx;
                int row = i2 / 17, c4 = i2 % 17;
                const float* src = (arr ? Vbase : Kbase) + (size_t)(l0 + row) * EH + 4 * c4;
                uint32_t dst = smem_u32(arr ? &vs[buf][row][4 * c4] : &ks[buf][row][4 * c4]);
                cp16(dst, src);
            }
        }
        CP_COMMIT();
    };

    issue(0);

    float acc[5][5] = {};
#pragma unroll 1
    for (int it = 0; it < LCHUNK / 16; it++) {
        CP_WAIT0();
        __syncthreads();
        if (it + 1 < LCHUNK / 16) issue(it + 1);
        const int buf = it & 1;
#pragma unroll
        for (int r = 0; r < 16; r++) {
            float kv[5], vv[5];
#pragma unroll
            for (int i = 0; i < 5; i++) kv[i] = ks[buf][r][td + 16 * i];
#pragma unroll
            for (int j = 0; j < 5; j++) vv[j] = vs[buf][r][te + 16 * j];
#pragma unroll
            for (int i = 0; i < 5; i++)
#pragma unroll
                for (int j = 0; j < 5; j++)
                    acc[i][j] += kv[i] * vv[j];
        }
        __syncthreads();
    }

    float* out = &g_part[(((size_t)b * Hc + h) * NSPLIT + split) * Ec * Ec];
#pragma unroll
    for (int i = 0; i < 5; i++) {
        int d = td + 16 * i;
        if (d >= Ec) continue;
#pragma unroll
        for (int j = 0; j < 5; j++) {
            int e = te + 16 * j;
            if (e < Ec) out[d * Ec + e] = acc[i][j];
        }
    }
}

// ============================================================================
// Kernel C: reduce partials, scale by 1/L
// ============================================================================
__global__ void attn_reduce(float* __restrict__ attn_out)
{
    const size_t idx = (size_t)blockIdx.x * blockDim.x + threadIdx.x;
    if (idx >= ATTN_ELEMS) return;
    const size_t bh = idx / (Ec * Ec);
    const size_t de = idx % (Ec * Ec);
    float s = 0.0f;
#pragma unroll
    for (int sp = 0; sp < NSPLIT; sp++)
        s += g_part[(bh * NSPLIT + sp) * (Ec * Ec) + de];
    attn_out[idx] = s * (1.0f / (float)Lc);
}

// ============================================================================
// Kernel D: W2T[b,o,h*65+d] = sum_e attn[b,h,d,e]*fcW[o,h*65+e]
// ============================================================================
__global__ void w2t_kernel(const float* __restrict__ attn, const float* __restrict__ fcW)
{
    const int bh = blockIdx.x;
    const int b = bh >> 3, h = bh & 7;
    __shared__ float a[Ec * Ec];
    const int tid = threadIdx.x;
    for (int i = tid; i < Ec * Ec; i += 256)
        a[i] = attn[(size_t)bh * Ec * Ec + i];
    __syncthreads();

    for (int o = tid; o < Dc; o += 256) {
        float w[Ec];
        const float* wr = &fcW[(size_t)o * Fc + h * Ec];
#pragma unroll
        for (int e = 0; e < Ec; e++) w[e] = wr[e];
        float* out = &g_W2T[((size_t)b * Dc + o) * FP + h * Ec];
#pragma unroll 1
        for (int d0 = 0; d0 < Ec; d0 += 5) {
            float s0 = 0, s1 = 0, s2 = 0, s3 = 0, s4 = 0;
#pragma unroll
            for (int e = 0; e < Ec; e++) {
                float we = w[e];
                s0 += a[(d0 + 0) * Ec + e] * we;
                s1 += a[(d0 + 1) * Ec + e] * we;
                s2 += a[(d0 + 2) * Ec + e] * we;
                s3 += a[(d0 + 3) * Ec + e] * we;
                s4 += a[(d0 + 4) * Ec + e] * we;
            }
            out[d0 + 0] = s0; out[d0 + 1] = s1; out[d0 + 2] = s2;
            out[d0 + 3] = s3; out[d0 + 4] = s4;
        }
    }
    if (h == 0) {
        for (int i = tid; i < Dc * (FP - Fc); i += 256) {
            int o = i / (FP - Fc), cc = Fc + i % (FP - Fc);
            g_W2T[((size_t)b * Dc + o) * FP + cc] = 0.0f;
        }
    }
}

// ============================================================================
// Kernel E: out[b] = QC[b] @ W2T[b]^T + fcb.  grid (4, 64, 4)
// ============================================================================
__global__ void __launch_bounds__(256)
out_gemm(const float* __restrict__ fcb, float* __restrict__ out)
{
    extern __shared__ __align__(16) float smf[];
    const uint32_t sbase = smem_u32(smf);
    const int b = blockIdx.z;
    const float* A  = g_QC + (size_t)b * Lc * FP;
    const float* Bw = g_W2T + (size_t)b * Dc * FP;
    float* C = out + (size_t)b * Lc * Dc;

    const int m0 = blockIdx.y * 128;
    const int n0 = blockIdx.x * 128;

    float acc[4][4][4] = {};
    gemm_mainloop(A, Bw, FP, FP / 32, m0, n0, smf, sbase, acc);

    const int tid = threadIdx.x;
    const int wid = tid >> 5;
    const int lane = tid & 31;
    const int g = lane >> 2;
    const int t = lane & 3;
    const int mw = (wid >> 2) * 64;
    const int nw = (wid & 3) * 32;

#pragma unroll
    for (int i = 0; i < 4; i++) {
        const int row0 = m0 + mw + 16 * i + g;
#pragma unroll
        for (int j = 0; j < 4; j++) {
            const int col = n0 + nw + 8 * j + 2 * t;
            float2 bv = *(const float2*)(fcb + col);
            float2 o0, o1;
            o0.x = acc[i][j][0] + bv.x;  o0.y = acc[i][j][1] + bv.y;
            o1.x = acc[i][j][2] + bv.x;  o1.y = acc[i][j][3] + bv.y;
            *(float2*)(C + (size_t)row0 * Dc + col) = o0;
            *(float2*)(C + (size_t)(row0 + 8) * Dc + col) = o1;
        }
    }
}

// ============================================================================
// launch
// ============================================================================
extern "C" void kernel_launch(void* const* d_in, const int* in_sizes, int n_in,
                              void* d_out, int out_size)
{
    const float* query = (const float*)d_in[0];
    const float* key   = (const float*)d_in[1];
    const float* value = (const float*)d_in[2];
    const float* pos   = (const float*)d_in[3];
    const float* Wq    = (const float*)d_in[4];
    const float* bq    = (const float*)d_in[5];
    const float* Wk    = (const float*)d_in[6];
    const float* bk    = (const float*)d_in[7];
    const float* Wv    = (const float*)d_in[8];
    const float* bv    = (const float*)d_in[9];
    const float* gK    = (const float*)d_in[10];
    const float* betaK = (const float*)d_in[11];
    const float* gV    = (const float*)d_in[12];
    const float* betaV = (const float*)d_in[13];
    const float* fcW   = (const float*)d_in[14];
    const float* fcb   = (const float*)d_in[15];

    float* att_out  = (float*)d_out;
    float* attn_out = att_out + ATT_ELEMS;

    cudaFuncSetAttribute(proj_fused, cudaFuncAttributeMaxDynamicSharedMemorySize, SMEM_GEMM);
    cudaFuncSetAttribute(out_gemm,  cudaFuncAttributeMaxDynamicSharedMemorySize, SMEM_GEMM);

    // 1) fused projections + LN + concat
    proj_fused<<<dim3(4, 256, 3), 256, SMEM_GEMM>>>(query, key, value,
                                                     Wq, bq, Wk, bk, Wv, bv,
                                                     gK, betaK, gV, betaV, pos);
    // 2) attn partials (deterministic split over L, fp32 exact)
    attn_partial<<<dim3(NSPLIT, Hc, Bc), 256>>>();
    // 3) reduce + scale -> attn output
    attn_reduce<<<(unsigned)((ATTN_ELEMS + 255) / 256), 256>>>(attn_out);
    // 4) fold attn into fc weights (transposed, K-major)
    w2t_kernel<<<Bc * Hc, 256>>>(attn_out, fcW);
    // 5) output GEMM, batched over z
    out_gemm<<<dim3(4, 64, Bc), 256, SMEM_GEMM>>>(fcb, att_out);
}

// round 5
// speedup vs baseline: 2.8322x; 1.2305x over previous
#include <cuda_runtime.h>
#include <cstdint>

// ---------------- problem constants ----------------
#define Bc 4
#define Lc 8192
#define Dc 512
#define Hc 8
#define DKc 64
#define Ec 65           // DK + PD
#define Fc 520          // H * E
#define FP 544          // padded F (multiple of 32)
#define EH 68           // padded per-head width for KH/VH (16B aligned)
#define NSPLIT 16
#define LCHUNK (Lc / NSPLIT)

#define ATT_ELEMS  ((size_t)Bc * Lc * Dc)
#define ATTN_ELEMS ((size_t)Bc * Hc * Ec * Ec)

// ---------------- scratch (device globals; no allocs allowed) ----------------
__device__ float g_QC[(size_t)Bc * Lc * FP];        // concat q [bl][FP], pad zeroed
__device__ float g_KH[(size_t)Bc * Hc * Lc * EH];   // LN'd k, head-major [b,h,l,68]
__device__ float g_VH[(size_t)Bc * Hc * Lc * EH];   // LN'd v, head-major
__device__ float g_part[(size_t)Bc * Hc * NSPLIT * Ec * Ec];
__device__ float g_W2T[(size_t)Bc * Dc * FP];       // attn folded into fcW, [b][o][f]

// ============================================================================
// helpers
// ============================================================================
__device__ __forceinline__ uint32_t smem_u32(const void* p) {
    uint32_t a;
    asm("{ .reg .u64 t; cvta.to.shared.u64 t, %1; cvt.u32.u64 %0, t; }" : "=r"(a) : "l"(p));
    return a;
}
__device__ __forceinline__ uint32_t f2tf32(float x) {
    uint32_t r;
    asm("cvt.rna.tf32.f32 %0, %1;" : "=r"(r) : "f"(x));
    return r;
}
__device__ __forceinline__ void cp16(uint32_t dst, const float* src) {
    asm volatile("cp.async.ca.shared.global [%0], [%1], 16;" :: "r"(dst), "l"(src));
}
#define CP_COMMIT() asm volatile("cp.async.commit_group;" ::: "memory")
#define CP_WAIT0()  asm volatile("cp.async.wait_group 0;" ::: "memory")
#define CP_WAIT1()  asm volatile("cp.async.wait_group 1;" ::: "memory")

__device__ __forceinline__ void mma_tf32(float c[4], const uint32_t a[4], const uint32_t b[2]) {
    asm volatile(
        "mma.sync.aligned.m16n8k8.row.col.f32.tf32.tf32.f32 "
        "{%0,%1,%2,%3}, {%4,%5,%6,%7}, {%8,%9}, {%0,%1,%2,%3};"
        : "+f"(c[0]), "+f"(c[1]), "+f"(c[2]), "+f"(c[3])
        : "r"(a[0]), "r"(a[1]), "r"(a[2]), "r"(a[3]), "r"(b[0]), "r"(b[1]));
}

// ============================================================================
// shared GEMM mainloop: acc[4][4][4] += A[m0..+128, :K] @ B[n0..+128, :K]^T
// 128x128 tile, K-block 32, cp.async 2-stage, tf32 cvt in consumer.
// 73.7KB smem -> 2 CTAs/SM.
// ============================================================================
#define SSTR 36                        // smem row stride (floats), conflict-free
#define ATILE (128 * SSTR)             // 4608 floats per operand per stage
#define STAGEF (2 * ATILE)             // 9216 floats per stage
#define NSTAGE 2
#define SMEM_GEMM (NSTAGE * STAGEF * 4)   // 73728 bytes

__device__ __forceinline__ void gemm_copy_stage(
    const float* __restrict__ A, const float* __restrict__ Bw,
    int lda, int m0, int n0, int kb, uint32_t sbase,
    int crow, int ccol)
{
    const int s = kb & 1;
    const int k0 = kb << 5;
    uint32_t as = sbase + (uint32_t)(s * STAGEF) * 4u;
    uint32_t bs = as + (uint32_t)ATILE * 4u;
    const float* ap = A + (size_t)(m0 + crow) * lda + k0 + ccol;
    const float* bp = Bw + (size_t)(n0 + crow) * lda + k0 + ccol;
    uint32_t doff = (uint32_t)(crow * SSTR + ccol) * 4u;
#pragma unroll
    for (int i = 0; i < 4; i++) {
        cp16(as + doff + 16u * i, ap + 4 * i);
        cp16(bs + doff + 16u * i, bp + 4 * i);
    }
}

__device__ __forceinline__ void gemm_mainloop(
    const float* __restrict__ A, const float* __restrict__ Bw,
    int lda, int NKB, int m0, int n0,
    float* smf, uint32_t sbase, float acc[4][4][4])
{
    const int tid = threadIdx.x;
    const int wid = tid >> 5;
    const int lane = tid & 31;
    const int g = lane >> 2;
    const int t = lane & 3;
    const int mw = (wid >> 2) * 64;
    const int nw = (wid & 3) * 32;

    const int crow = tid >> 1;            // copy row 0..127
    const int ccol = (tid & 1) << 4;      // 0 or 16 floats

    // prologue: stage 0 (+1)
    gemm_copy_stage(A, Bw, lda, m0, n0, 0, sbase, crow, ccol);
    CP_COMMIT();
    if (NKB > 1) {
        gemm_copy_stage(A, Bw, lda, m0, n0, 1, sbase, crow, ccol);
        CP_COMMIT();
    }

#pragma unroll 1
    for (int kb = 0; kb < NKB; kb++) {
        if (kb + 1 < NKB) { CP_WAIT1(); } else { CP_WAIT0(); }
        __syncthreads();

        // compute stage kb&1
        const float* As = smf + (kb & 1) * STAGEF;
        const float* Bs = As + ATILE;
#pragma unroll
        for (int kk = 0; kk < 32; kk += 8) {
            uint32_t af[4][4];
#pragma unroll
            for (int i = 0; i < 4; i++) {
                const float* base = As + (mw + 16 * i) * SSTR + kk;
                af[i][0] = f2tf32(base[(g)     * SSTR + t]);
                af[i][1] = f2tf32(base[(g + 8) * SSTR + t]);
                af[i][2] = f2tf32(base[(g)     * SSTR + t + 4]);
                af[i][3] = f2tf32(base[(g + 8) * SSTR + t + 4]);
            }
            uint32_t bf[4][2];
#pragma unroll
            for (int j = 0; j < 4; j++) {
                const float* base = Bs + (nw + 8 * j + g) * SSTR + kk;
                bf[j][0] = f2tf32(base[t]);
                bf[j][1] = f2tf32(base[t + 4]);
            }
#pragma unroll
            for (int i = 0; i < 4; i++)
#pragma unroll
                for (int j = 0; j < 4; j++)
                    mma_tf32(acc[i][j], af[i], bf[j]);
        }
        __syncthreads();

        // issue copy for kb+2 (writes buffer kb&1, now free on all warps)
        if (kb + 2 < NKB) {
            gemm_copy_stage(A, Bw, lda, m0, n0, kb + 2, sbase, crow, ccol);
            CP_COMMIT();
        }
    }
}

// ============================================================================
// Kernel A: fused projection + LN + concat.  grid (4, 256, 3), 256 thr.
// z=0: q -> g_QC (concat, pad);  z=1: k -> g_KH (LN);  z=2: v -> g_VH (LN)
// ============================================================================
#define CSTR 132

__global__ void __launch_bounds__(256, 2)
proj_fused(const float* __restrict__ Xq, const float* __restrict__ Xk,
           const float* __restrict__ Xv,
           const float* __restrict__ Wq, const float* __restrict__ bq,
           const float* __restrict__ Wk, const float* __restrict__ bk,
           const float* __restrict__ Wv, const float* __restrict__ bv,
           const float* __restrict__ gK, const float* __restrict__ betaK,
           const float* __restrict__ gV, const float* __restrict__ betaV,
           const float* __restrict__ pos)
{
    extern __shared__ __align__(16) float smf[];
    const uint32_t sbase = smem_u32(smf);
    const int mode = blockIdx.z;
    const float* A    = (mode == 0) ? Xq : (mode == 1) ? Xk : Xv;
    const float* W    = (mode == 0) ? Wq : (mode == 1) ? Wk : Wv;
    const float* bias = (mode == 0) ? bq : (mode == 1) ? bk : bv;
    const float* gamm = (mode == 1) ? gK : gV;
    const float* beta = (mode == 1) ? betaK : betaV;

    const int m0 = blockIdx.y * 128;
    const int n0 = blockIdx.x * 128;

    float acc[4][4][4] = {};
    gemm_mainloop(A, W, Dc, Dc / 32, m0, n0, smf, sbase, acc);

    // ---- stage tile (+bias) into smem ----
    __syncthreads();
    const int tid = threadIdx.x;
    const int wid = tid >> 5;
    const int lane = tid & 31;
    const int g = lane >> 2;
    const int t = lane & 3;
    const int mw = (wid >> 2) * 64;
    const int nw = (wid & 3) * 32;

#pragma unroll
    for (int i = 0; i < 4; i++) {
        const int r0 = mw + 16 * i + g;
#pragma unroll
        for (int j = 0; j < 4; j++) {
            const int col = nw + 8 * j + 2 * t;
            float2 bv2 = *(const float2*)(bias + n0 + col);
            smf[r0 * CSTR + col]       = acc[i][j][0] + bv2.x;
            smf[r0 * CSTR + col + 1]   = acc[i][j][1] + bv2.y;
            smf[(r0 + 8) * CSTR + col]     = acc[i][j][2] + bv2.x;
            smf[(r0 + 8) * CSTR + col + 1] = acc[i][j][3] + bv2.y;
        }
    }
    __syncthreads();

    // ---- per-row epilogue: 8 warps x 16 rows ----
    for (int rr = 0; rr < 16; rr++) {
        const int r = wid * 16 + rr;
        const int m = m0 + r;                 // = b*L + l
        const int b = m >> 13, l = m & (Lc - 1);
        const float pv = pos[m];
#pragma unroll
        for (int hh = 0; hh < 2; hh++) {
            const int h = (n0 >> 6) + hh;
            float x0 = smf[r * CSTR + 64 * hh + lane];
            float x1 = smf[r * CSTR + 64 * hh + lane + 32];
            if (mode == 0) {
                float* qrow = &g_QC[(size_t)m * FP + h * Ec];
                if (lane == 0) qrow[0] = pv;
                qrow[1 + lane] = x0;
                qrow[1 + lane + 32] = x1;
                if (hh == 1 && n0 == 384 && lane < (FP - Fc))
                    g_QC[(size_t)m * FP + Fc + lane] = 0.0f;
            } else {
                float s = x0 + x1, sq = x0 * x0 + x1 * x1;
#pragma unroll
                for (int off = 16; off; off >>= 1) {
                    s  += __shfl_xor_sync(0xffffffffu, s,  off);
                    sq += __shfl_xor_sync(0xffffffffu, sq, off);
                }
                float mean = s * (1.0f / 64.0f);
                float var = sq * (1.0f / 64.0f) - mean * mean;
                float rstd = rsqrtf(var + 1e-5f);
                float y0 = (x0 - mean) * rstd * gamm[h * DKc + lane] + beta[h * DKc + lane];
                float y1 = (x1 - mean) * rstd * gamm[h * DKc + lane + 32] + beta[h * DKc + lane + 32];
                float* orow = ((mode == 1) ? g_KH : g_VH) +
                              (((size_t)b * Hc + h) * Lc + l) * EH;
                if (lane == 0) orow[0] = pv;
                orow[1 + lane] = y0;
                orow[1 + lane + 32] = y1;
                if (lane < 2) orow[66 + lane] = 0.0f;   // pad cols
            }
        }
    }
}

// ============================================================================
// Kernel B: attn partials  part[b,h,s] = K_chunk^T @ V_chunk  (fp32 exact)
// ============================================================================
__global__ void __launch_bounds__(256)
attn_partial()
{
    __shared__ __align__(16) float ks[2][16][80];
    __shared__ __align__(16) float vs[2][16][80];
    const int split = blockIdx.x, h = blockIdx.y, b = blockIdx.z;
    const int tid = threadIdx.x;
    const int td = tid >> 4;
    const int te = tid & 15;

    for (int i = tid; i < 2 * 16 * 80; i += 256) {
        ((float*)ks)[i] = 0.0f;
        ((float*)vs)[i] = 0.0f;
    }
    __syncthreads();

    const float* Kbase = g_KH + (((size_t)b * Hc + h) * Lc + (size_t)split * LCHUNK) * EH;
    const float* Vbase = g_VH + (((size_t)b * Hc + h) * Lc + (size_t)split * LCHUNK) * EH;

    auto issue = [&](int it) {
        const int buf = it & 1;
        const int l0 = it * 16;
#pragma unroll
        for (int c = 0; c < 3; c++) {
            int idx = tid + c * 256;
            if (idx < 544) {
                int arr = idx >= 272;
                int i2 = arr ? idx - 272 : idx;
                int row = i2 / 17, c4 = i2 % 17;
                const float* src = (arr ? Vbase : Kbase) + (size_t)(l0 + row) * EH + 4 * c4;
                uint32_t dst = smem_u32(arr ? &vs[buf][row][4 * c4] : &ks[buf][row][4 * c4]);
                cp16(dst, src);
            }
        }
        CP_COMMIT();
    };

    issue(0);

    float acc[5][5] = {};
#pragma unroll 1
    for (int it = 0; it < LCHUNK / 16; it++) {
        CP_WAIT0();
        __syncthreads();
        if (it + 1 < LCHUNK / 16) issue(it + 1);
        const int buf = it & 1;
#pragma unroll
        for (int r = 0; r < 16; r++) {
            float kv[5], vv[5];
#pragma unroll
            for (int i = 0; i < 5; i++) kv[i] = ks[buf][r][td + 16 * i];
#pragma unroll
            for (int j = 0; j < 5; j++) vv[j] = vs[buf][r][te + 16 * j];
#pragma unroll
            for (int i = 0; i < 5; i++)
#pragma unroll
                for (int j = 0; j < 5; j++)
                    acc[i][j] += kv[i] * vv[j];
        }
        __syncthreads();
    }

    float* out = &g_part[(((size_t)b * Hc + h) * NSPLIT + split) * Ec * Ec];
#pragma unroll
    for (int i = 0; i < 5; i++) {
        int d = td + 16 * i;
        if (d >= Ec) continue;
#pragma unroll
        for (int j = 0; j < 5; j++) {
            int e = te + 16 * j;
            if (e < Ec) out[d * Ec + e] = acc[i][j];
        }
    }
}

// ============================================================================
// Kernel C: reduce partials, scale by 1/L
// ============================================================================
__global__ void attn_reduce(float* __restrict__ attn_out)
{
    const size_t idx = (size_t)blockIdx.x * blockDim.x + threadIdx.x;
    if (idx >= ATTN_ELEMS) return;
    const size_t bh = idx / (Ec * Ec);
    const size_t de = idx % (Ec * Ec);
    float s = 0.0f;
#pragma unroll
    for (int sp = 0; sp < NSPLIT; sp++)
        s += g_part[(bh * NSPLIT + sp) * (Ec * Ec) + de];
    attn_out[idx] = s * (1.0f / (float)Lc);
}

// ============================================================================
// Kernel D: W2T[b,o,h*65+d] = sum_e attn[b,h,d,e]*fcW[o,h*65+e]
// grid (8, 32): 64 o's per block; all operands staged in smem.
// ============================================================================
__global__ void __launch_bounds__(256)
w2t_kernel(const float* __restrict__ attn, const float* __restrict__ fcW)
{
    const int og = blockIdx.x;          // 0..7 (64 o's each)
    const int bh = blockIdx.y;          // 0..31
    const int b = bh >> 3, h = bh & 7;
    __shared__ float sa[Ec * 66];       // attn[d][e]
    __shared__ float sw[64 * 66];       // fcW[o][e]
    const int tid = threadIdx.x;

    for (int i = tid; i < Ec * Ec; i += 256) {
        int d = i / Ec, e = i % Ec;
        sa[d * 66 + e] = attn[((size_t)bh * Ec + d) * Ec + e];
    }
    for (int i = tid; i < 64 * Ec; i += 256) {
        int o = i / Ec, e = i % Ec;
        sw[o * 66 + e] = fcW[(size_t)(og * 64 + o) * Fc + h * Ec + e];
    }
    __syncthreads();

    for (int idx = tid; idx < 64 * Ec; idx += 256) {
        int o = idx / Ec, d = idx % Ec;
        const float* wr = &sw[o * 66];
        const float* ar = &sa[d * 66];
        float s = 0.0f;
#pragma unroll
        for (int e = 0; e < Ec; e++) s += wr[e] * ar[e];
        g_W2T[((size_t)b * Dc + og * 64 + o) * FP + h * Ec + d] = s;
    }
    // zero pad cols [Fc, FP)
    if (h == 0) {
        for (int i = tid; i < 64 * (FP - Fc); i += 256) {
            int o = og * 64 + i / (FP - Fc), cc = Fc + i % (FP - Fc);
            g_W2T[((size_t)b * Dc + o) * FP + cc] = 0.0f;
        }
    }
}

// ============================================================================
// Kernel E: out[b] = QC[b] @ W2T[b]^T + fcb.  grid (4, 64, 4)
// ============================================================================
__global__ void __launch_bounds__(256, 2)
out_gemm(const float* __restrict__ fcb, float* __restrict__ out)
{
    extern __shared__ __align__(16) float smf[];
    const uint32_t sbase = smem_u32(smf);
    const int b = blockIdx.z;
    const float* A  = g_QC + (size_t)b * Lc * FP;
    const float* Bw = g_W2T + (size_t)b * Dc * FP;
    float* C = out + (size_t)b * Lc * Dc;

    const int m0 = blockIdx.y * 128;
    const int n0 = blockIdx.x * 128;

    float acc[4][4][4] = {};
    gemm_mainloop(A, Bw, FP, FP / 32, m0, n0, smf, sbase, acc);

    const int tid = threadIdx.x;
    const int wid = tid >> 5;
    const int lane = tid & 31;
    const int g = lane >> 2;
    const int t = lane & 3;
    const int mw = (wid >> 2) * 64;
    const int nw = (wid & 3) * 32;

#pragma unroll
    for (int i = 0; i < 4; i++) {
        const int row0 = m0 + mw + 16 * i + g;
#pragma unroll
        for (int j = 0; j < 4; j++) {
            const int col = n0 + nw + 8 * j + 2 * t;
            float2 bv = *(const float2*)(fcb + col);
            float2 o0, o1;
            o0.x = acc[i][j][0] + bv.x;  o0.y = acc[i][j][1] + bv.y;
            o1.x = acc[i][j][2] + bv.x;  o1.y = acc[i][j][3] + bv.y;
            *(float2*)(C + (size_t)row0 * Dc + col) = o0;
            *(float2*)(C + (size_t)(row0 + 8) * Dc + col) = o1;
        }
    }
}

// ============================================================================
// launch
// ============================================================================
extern "C" void kernel_launch(void* const* d_in, const int* in_sizes, int n_in,
                              void* d_out, int out_size)
{
    const float* query = (const float*)d_in[0];
    const float* key   = (const float*)d_in[1];
    const float* value = (const float*)d_in[2];
    const float* pos   = (const float*)d_in[3];
    const float* Wq    = (const float*)d_in[4];
    const float* bq    = (const float*)d_in[5];
    const float* Wk    = (const float*)d_in[6];
    const float* bk    = (const float*)d_in[7];
    const float* Wv    = (const float*)d_in[8];
    const float* bv    = (const float*)d_in[9];
    const float* gK    = (const float*)d_in[10];
    const float* betaK = (const float*)d_in[11];
    const float* gV    = (const float*)d_in[12];
    const float* betaV = (const float*)d_in[13];
    const float* fcW   = (const float*)d_in[14];
    const float* fcb   = (const float*)d_in[15];

    float* att_out  = (float*)d_out;
    float* attn_out = att_out + ATT_ELEMS;

    cudaFuncSetAttribute(proj_fused, cudaFuncAttributeMaxDynamicSharedMemorySize, SMEM_GEMM);
    cudaFuncSetAttribute(out_gemm,  cudaFuncAttributeMaxDynamicSharedMemorySize, SMEM_GEMM);

    // 1) fused projections + LN + concat
    proj_fused<<<dim3(4, 256, 3), 256, SMEM_GEMM>>>(query, key, value,
                                                     Wq, bq, Wk, bk, Wv, bv,
                                                     gK, betaK, gV, betaV, pos);
    // 2) attn partials (deterministic split over L, fp32 exact)
    attn_partial<<<dim3(NSPLIT, Hc, Bc), 256>>>();
    // 3) reduce + scale -> attn output
    attn_reduce<<<(unsigned)((ATTN_ELEMS + 255) / 256), 256>>>(attn_out);
    // 4) fold attn into fc weights (parallel, smem-staged)
    w2t_kernel<<<dim3(8, Bc * Hc), 256>>>(attn_out, fcW);
    // 5) output GEMM, batched over z
    out_gemm<<<dim3(4, 64, Bc), 256, SMEM_GEMM>>>(fcb, att_out);
}